// round 17
// baseline (speedup 1.0000x reference)
#include <cuda_runtime.h>

#define IN_DIM   8192
#define OUT_DIM  16384
#define TOP_K    327
#define NSLICE   16
#define NPACK    (OUT_DIM / 4)        // 4096 u64 words per buffer (= 2048 int4)

// Parity-double-buffered packed accumulator. Launch with parity q:
//   k_gemv accumulates into g_pack[q]  (zeroed two launches ago / statically)
//   k_sel  reads g_pack[q] and zeroes ALL of g_pack[q^1] (idle this launch).
//   The 16th k_sel block to arrive at the end ticket flips g_parity; every
//   block read q at its start before arriving, so the flip is race-free.
// Each u64 packs 4 16-bit counters (counts <= 8192, no cross-field carries).
__device__ unsigned long long g_pack[2][NPACK];
__device__ int g_parity;
__device__ int g_fin;

#define GEMV_TB     256
#define STRIP       128
#define ROW_STRIPS  (IN_DIM / STRIP)        // 64
#define COLS_BLK    (GEMV_TB * 4)           // 1024
#define COL_TILES   (OUT_DIM / COLS_BLK)    // 16

// ---------------------------------------------------------------------------
// k_gemv: overlap[c] += sum over active rows of (p[row][c] > 0.5f)
//   grid = (16 col tiles, 64 row strips), 256 threads. Ballot-compacts its
//   own 128-row strip of x, streams active rows' float4 column slices.
//   ~5.9-6.0 TB/s: at the DRAM/LTS roofline. One packed u64 atomic/thread.
// ---------------------------------------------------------------------------
__global__ __launch_bounds__(GEMV_TB, 7) void k_gemv(const int* __restrict__ x,
                                                     const float* __restrict__ p) {
    __shared__ int srows[STRIP];
    __shared__ int s_wcnt[4];

    const int t    = threadIdx.x;
    const int lane = t & 31;
    const int w    = t >> 5;
    const int r0   = blockIdx.y * STRIP;
    const int q    = g_parity;

    int a = 0, myrow = 0;
    unsigned m = 0;
    if (w < 4) {
        myrow = r0 + t;
        a = (x[myrow] != 0);
        m = __ballot_sync(0xffffffffu, a);
        if (lane == 0) s_wcnt[w] = __popc(m);
    }
    __syncthreads();
    const int nr = s_wcnt[0] + s_wcnt[1] + s_wcnt[2] + s_wcnt[3];
    if (w < 4 && a) {
        int off = 0;
        #pragma unroll
        for (int i = 0; i < 4; i++) if (i < w) off += s_wcnt[i];
        int rank = __popc(m & ((1u << lane) - 1u));
        srows[off + rank] = myrow;
    }
    __syncthreads();
    if (nr == 0) return;

    const int col4 = blockIdx.x * GEMV_TB + t;   // float4 index == u64 word index
    const float4* __restrict__ p4 = (const float4*)p;
    const long stride4 = OUT_DIM / 4;

    int c0 = 0, c1 = 0, c2 = 0, c3 = 0;

    int r = 0;
    #pragma unroll 1
    for (; r + 4 <= nr; r += 4) {
        #pragma unroll
        for (int u = 0; u < 4; u++) {
            const int row = srows[r + u];
            const float4 v = __ldg(&p4[(long)row * stride4 + col4]);
            c0 += (v.x > 0.5f);
            c1 += (v.y > 0.5f);
            c2 += (v.z > 0.5f);
            c3 += (v.w > 0.5f);
        }
    }
    for (; r < nr; r++) {
        const int row = srows[r];
        const float4 v = __ldg(&p4[(long)row * stride4 + col4]);
        c0 += (v.x > 0.5f);
        c1 += (v.y > 0.5f);
        c2 += (v.z > 0.5f);
        c3 += (v.w > 0.5f);
    }

    const unsigned lohalf = (unsigned)c0 | ((unsigned)c1 << 16);
    const unsigned hihalf = (unsigned)c2 | ((unsigned)c3 << 16);
    const unsigned long long pv = (unsigned long long)lohalf |
                                  ((unsigned long long)hihalf << 32);
    atomicAdd(&g_pack[q][col4], pv);
}

// ---------------------------------------------------------------------------
// k_sel: 16 blocks x 1024 threads. Every block redundantly loads the full
// packed overlap (32 KB, 16 values/thread), selects T/rem via coarse(257 x
// width-32, 16 bank-staggered copies) + fine(32) histograms, computes the
// jax tie rank via a block-wide exclusive scan (thread order == index
// order), emits its own 1024-col slice, zeroes its 1/16 of the OTHER
// parity buffer (full 2048 int4 across blocks), last block flips g_parity.
// ---------------------------------------------------------------------------
#define SEL_TB    1024
#define NC        257
#define WH_COPIES 16
#define WH_STRIDE 261   // staggered stride: hot bins of copies -> distinct banks

__global__ __launch_bounds__(SEL_TB) void k_sel(float* __restrict__ out) {
    __shared__ int s_wh[WH_COPIES * WH_STRIDE];  // ~16.3 KB
    __shared__ int s_coarse[NC];
    __shared__ int s_fine[32];
    __shared__ int s_w[32], s_wab[32], s_w2[32];
    __shared__ int s_C, s_cum, s_T, s_rem;

    const int t    = threadIdx.x;
    const int lane = t & 31;
    const int wid  = t >> 5;
    const int blk  = blockIdx.x;
    const int copy = wid >> 1;                   // 16 copies, 2 warps each
    const int q    = g_parity;

    // ---- load all 16384 values: 2 int4 = 8 packed ints = 16 values ----
    const int4* gp = (const int4*)g_pack[q];
    const int4 a0 = __ldcg(gp + 2 * t);
    const int4 a1 = __ldcg(gp + 2 * t + 1);
    int va[16];
    {
        const int w8[8] = {a0.x, a0.y, a0.z, a0.w, a1.x, a1.y, a1.z, a1.w};
        #pragma unroll
        for (int i = 0; i < 8; i++) {
            va[2 * i + 0] = w8[i] & 0xffff;
            va[2 * i + 1] = (int)((unsigned)w8[i] >> 16);
        }
    }

    // ---- coarse histogram (bins of width 32), 16 bank-staggered copies ----
    for (int i = t; i < WH_COPIES * WH_STRIDE; i += SEL_TB) s_wh[i] = 0;
    if (t < 32) s_fine[t] = 0;
    __syncthreads();
    {
        int* my = s_wh + copy * WH_STRIDE;
        #pragma unroll
        for (int j = 0; j < 16; j++) atomicAdd(&my[va[j] >> 5], 1);
    }
    __syncthreads();
    if (t < NC) {
        int s = 0;
        #pragma unroll
        for (int c = 0; c < WH_COPIES; c++) s += s_wh[c * WH_STRIDE + t];
        s_coarse[t] = s;
    }
    __syncthreads();

    // ---- suffix scan over coarse bins (uniform control flow; threads >=
    //      256 participate with loc = 0) ----
    {
        int c255 = 0, c256 = 0, loc = 0;
        if (t < 256) {
            if (t == 255) {
                c255 = s_coarse[255];
                c256 = s_coarse[256];
                loc  = c255 + c256;
            } else {
                loc = s_coarse[t];
            }
        }

        int suf = loc;
        #pragma unroll
        for (int off = 1; off < 32; off <<= 1) {
            int v = __shfl_down_sync(0xffffffffu, suf, off);
            if (lane + off < 32) suf += v;
        }
        if (lane == 0) s_w[wid] = suf;
        __syncthreads();
        if (wid == 0) {
            int wv = (lane < 8) ? s_w[lane] : 0;
            int ws = wv;
            #pragma unroll
            for (int off = 1; off < 32; off <<= 1) {
                int v = __shfl_down_sync(0xffffffffu, ws, off);
                if (lane + off < 32) ws += v;
            }
            s_wab[lane] = ws - wv;
        }
        __syncthreads();
        if (t < 256) {
            const int above = s_wab[wid] + (suf - loc);
            if (above < TOP_K && above + loc >= TOP_K) {
                int C, cum;
                if (t == 255) {
                    if (above + c256 >= TOP_K) { C = 256; cum = above; }
                    else                       { C = 255; cum = above + c256; }
                } else { C = t; cum = above; }
                s_C = C; s_cum = cum;
            }
        }
    }
    __syncthreads();
    const int C        = s_C;
    const int cumAbove = s_cum;

    // ---- fine histogram inside coarse bin C ----
    #pragma unroll
    for (int j = 0; j < 16; j++) {
        unsigned d = (unsigned)(va[j] - (C << 5));
        if (d < 32u) atomicAdd(&s_fine[d], 1);
    }
    __syncthreads();
    if (t == 0) {
        int acc = cumAbove, T = 0, rem = 0;
        for (int i = 31; i >= 0; i--) {
            int h = s_fine[i];
            if (acc < TOP_K && acc + h >= TOP_K) {
                T = (C << 5) + i; rem = TOP_K - acc; break;
            }
            acc += h;
        }
        s_T = T; s_rem = rem;
    }
    __syncthreads();
    const int T   = s_T;
    const int rem = s_rem;

    // ---- block-wide exclusive scan of tie counts (index order) ----
    int cnt = 0;
    #pragma unroll
    for (int j = 0; j < 16; j++) cnt += (va[j] == T);

    int inc = cnt;
    #pragma unroll
    for (int o = 1; o < 32; o <<= 1) {
        int n = __shfl_up_sync(0xffffffffu, inc, o);
        if (lane >= o) inc += n;
    }
    if (lane == 31) s_w2[wid] = inc;
    __syncthreads();
    if (wid == 0) {
        int tot = s_w2[lane];
        int sv = tot;
        #pragma unroll
        for (int o = 1; o < 32; o <<= 1) {
            int n = __shfl_up_sync(0xffffffffu, sv, o);
            if (lane >= o) sv += n;
        }
        s_w2[lane] = sv - tot;
    }
    __syncthreads();
    int run = s_w2[wid] + (inc - cnt);   // global tie rank of my first value

    // ---- emit my slice (threads 64*blk .. 64*blk+63 own it) ----
    const bool owner = (t >= 64 * blk) && (t < 64 * blk + 64);
    if (owner) {
        float4* o4 = (float4*)out + 4 * t;
        #pragma unroll
        for (int qq = 0; qq < 4; qq++) {
            float r[4];
            #pragma unroll
            for (int j = 0; j < 4; j++) {
                int vv = va[4 * qq + j];
                float o;
                if (vv > T) {
                    o = 1.0f;
                } else if (vv == T) {
                    o = (run < rem) ? 1.0f : 0.0f;
                    run++;
                } else {
                    o = 0.0f;
                }
                r[j] = o;
            }
            o4[qq] = make_float4(r[0], r[1], r[2], r[3]);
        }
    }

    // ---- zero my 1/16 of the OTHER parity buffer. Buffer = 2048 int4,
    //      so each of the 16 blocks zeroes 128 int4 (t < 128). ----
    {
        int4* ob = (int4*)g_pack[q ^ 1];
        if (t < 128) ob[blk * 128 + t] = make_int4(0, 0, 0, 0);
    }

    // 16th block to arrive flips parity for the next launch (no spin).
    // Safe: every block read q at kernel start before arriving here.
    if (t == 0) {
        if (atomicAdd(&g_fin, 1) == NSLICE - 1) {
            g_fin    = 0;
            g_parity = q ^ 1;
        }
    }
}

// ---------------------------------------------------------------------------
extern "C" void kernel_launch(void* const* d_in, const int* in_sizes, int n_in,
                              void* d_out, int out_size) {
    const int*   x = (const int*)d_in[0];   // [1, 8192] int32
    const float* p = (const float*)d_in[1]; // [8192, 16384] float32
    float* out = (float*)d_out;             // [1, 16384] float32

    dim3 grid(COL_TILES, ROW_STRIPS);
    k_gemv<<<grid, GEMV_TB>>>(x, p);
    k_sel<<<NSLICE, SEL_TB>>>(out);
}